// round 1
// baseline (speedup 1.0000x reference)
#include <cuda_runtime.h>
#include <math.h>

#define SS 64
#define NN 256
#define CC 3
#define BB 64
#define LL 2048
#define WW (LL - SS + 1)  /* 1985 */
#define NT 32             /* n per block */
#define WPT 8             /* w per thread per chunk */
#define THREADS 256

__device__ float g_winsq[BB * CC * WW];

// Kernel 1: precompute sliding window squared norms win_sq[b][c][w]
__global__ void winsq_kernel(const float* __restrict__ x) {
    int b = blockIdx.x;
    int c = blockIdx.y;
    __shared__ float xs[LL];
    const float* xp = x + (b * CC + c) * LL;
    for (int i = threadIdx.x; i < LL; i += blockDim.x) xs[i] = xp[i];
    __syncthreads();
    for (int w = threadIdx.x; w < WW; w += blockDim.x) {
        float s = 0.f;
#pragma unroll 16
        for (int k = 0; k < SS; k++) { float v = xs[w + k]; s = fmaf(v, v, s); }
        g_winsq[(b * CC + c) * WW + w] = s;
    }
}

// Kernel 2: main — per block: one b, 32 shapelets; min over all w
__global__ __launch_bounds__(THREADS, 2) void main_kernel(
    const float* __restrict__ x, const float* __restrict__ shp,
    float* __restrict__ out)
{
    extern __shared__ float smem[];
    float* xs  = smem;                  // CC * LL          = 6144
    float* shs = xs + CC * LL;          // CC * NT * 65     = 6240 (pad 65 vs bank conflicts)
    float* ws  = shs + CC * NT * 65;    // CC * WW          = 5955
    float* sq  = ws + CC * WW;          // CC * NT          = 96

    int b = blockIdx.y;
    int ntile = blockIdx.x;
    int tid = threadIdx.x;

    // Stage x rows for this batch
    for (int i = tid; i < CC * LL; i += THREADS)
        xs[i] = x[b * CC * LL + i];
    // Stage shapelet tile (padded rows)
    for (int i = tid; i < CC * NT * SS; i += THREADS) {
        int c = i / (NT * SS);
        int r = i % (NT * SS);
        int n = r / SS, s = r % SS;
        shs[(c * NT + n) * 65 + s] = shp[(c * NN + ntile * NT + n) * SS + s];
    }
    // Stage win_sq
    for (int i = tid; i < CC * WW; i += THREADS)
        ws[i] = g_winsq[b * CC * WW + i];
    __syncthreads();

    // Shapelet squared norms for the tile
    if (tid < CC * NT) {
        int c = tid / NT, n = tid % NT;
        float s = 0.f;
#pragma unroll 16
        for (int k = 0; k < SS; k++) {
            float v = shs[(c * NT + n) * 65 + k];
            s = fmaf(v, v, s);
        }
        sq[tid] = s;
    }
    __syncthreads();

    int wg = tid & 7;    // w-group (lane bits 0..2)
    int nl = tid >> 3;   // local shapelet index 0..31
    float tmin = INFINITY;

    const int NCHUNK = (WW + 63) / 64;  // 32
    for (int chunk = 0; chunk < NCHUNK; chunk++) {
        int w0 = chunk * 64 + wg * WPT;
        float total[WPT];
#pragma unroll
        for (int j = 0; j < WPT; j++) total[j] = 0.f;

#pragma unroll
        for (int c = 0; c < CC; c++) {
            const float* xc = xs + c * LL;
            // Register-resident x window: x[w0 .. w0+70], clamped in range
            float xr[WPT + SS - 1];
#pragma unroll
            for (int k = 0; k < WPT + SS - 1; k++)
                xr[k] = xc[min(w0 + k, LL - 1)];

            float acc[WPT];
#pragma unroll
            for (int j = 0; j < WPT; j++) acc[j] = 0.f;

            const float* shn = shs + (c * NT + nl) * 65;
#pragma unroll
            for (int s = 0; s < SS; s++) {
                float shv = shn[s];
#pragma unroll
                for (int j = 0; j < WPT; j++)
                    acc[j] = fmaf(xr[s + j], shv, acc[j]);
            }

            float sqn = sq[c * NT + nl];
#pragma unroll
            for (int j = 0; j < WPT; j++) {
                int wi = min(w0 + j, WW - 1);
                float d2 = ws[c * WW + wi] + sqn - 2.f * acc[j];
                total[j] += sqrtf(fmaxf(d2, 0.f));
            }
        }
#pragma unroll
        for (int j = 0; j < WPT; j++)
            if (w0 + j < WW) tmin = fminf(tmin, total[j]);
    }

    // Min-reduce across the 8 w-group lanes (lane bits 0..2)
#pragma unroll
    for (int m = 1; m < 8; m <<= 1)
        tmin = fminf(tmin, __shfl_xor_sync(0xffffffffu, tmin, m));

    if (wg == 0)
        out[b * NN + ntile * NT + nl] = tmin;
}

extern "C" void kernel_launch(void* const* d_in, const int* in_sizes, int n_in,
                              void* d_out, int out_size) {
    (void)in_sizes; (void)n_in; (void)out_size;
    const float* x   = (const float*)d_in[0];
    const float* shp = (const float*)d_in[1];
    float* out = (float*)d_out;

    const int smem_bytes = (CC * LL + CC * NT * 65 + CC * WW + CC * NT) * (int)sizeof(float);
    cudaFuncSetAttribute(main_kernel, cudaFuncAttributeMaxDynamicSharedMemorySize, smem_bytes);

    winsq_kernel<<<dim3(BB, CC), 256>>>(x);
    main_kernel<<<dim3(NN / NT, BB), THREADS, smem_bytes>>>(x, shp, out);
}

// round 2
// speedup vs baseline: 3.2383x; 3.2383x over previous
#include <cuda_runtime.h>
#include <math.h>

#define SS 64
#define NN 256
#define CC 3
#define BB 64
#define LL 2048
#define WW (LL - SS + 1)   /* 1985 */
#define WPAD 2048          /* padded winsq row stride */
#define NT 32              /* shapelets per block (16 pairs) */
#define NPAIR 16
#define WG 16              /* w-groups per block */
#define WPT 8              /* w per thread */
#define WSPLIT 4           /* w-range splits (blocks per (b,ntile)) */
#define NCHUNK_TOT 16      /* ceil(1985/128) */
#define CHUNK_PER_BLK (NCHUNK_TOT / WSPLIT)
#define THREADS 256

__device__ float g_winsq[BB * CC * WPAD];

// ---------- packed f32x2 helpers (sm_103a) ----------
__device__ __forceinline__ unsigned long long pack2(float v) {
    unsigned long long r;
    asm("mov.b64 %0, {%1, %1};" : "=l"(r) : "f"(v));
    return r;
}
__device__ __forceinline__ void fma2(unsigned long long& d, unsigned long long a,
                                     unsigned long long b) {
    asm("fma.rn.f32x2 %0, %1, %2, %0;" : "+l"(d) : "l"(a), "l"(b));
}
__device__ __forceinline__ unsigned long long add2(unsigned long long a,
                                                   unsigned long long b) {
    unsigned long long r;
    asm("add.rn.f32x2 %0, %1, %2;" : "=l"(r) : "l"(a), "l"(b));
    return r;
}
__device__ __forceinline__ void unpack2(float& lo, float& hi, unsigned long long v) {
    asm("mov.b64 {%0, %1}, %2;" : "=f"(lo), "=f"(hi) : "l"(v));
}

// ---------- kernel 0: init output to +inf ----------
__global__ void init_kernel(float* out) {
    int i = blockIdx.x * blockDim.x + threadIdx.x;
    if (i < BB * NN) out[i] = __int_as_float(0x7f800000);
}

// ---------- kernel 1: window squared norms (padded rows) ----------
__global__ void winsq_kernel(const float* __restrict__ x) {
    int b = blockIdx.x, c = blockIdx.y;
    __shared__ float xs[LL];
    const float* xp = x + (b * CC + c) * LL;
    for (int i = threadIdx.x; i < LL; i += blockDim.x) xs[i] = xp[i];
    __syncthreads();
    for (int w = threadIdx.x; w < WPAD; w += blockDim.x) {
        float s = 0.f;
        if (w < WW) {
#pragma unroll 16
            for (int k = 0; k < SS; k++) { float v = xs[w + k]; s = fmaf(v, v, s); }
        }
        g_winsq[(b * CC + c) * WPAD + w] = s;
    }
}

// ---------- kernel 2: main ----------
__global__ __launch_bounds__(THREADS, 2) void main_kernel(
    const float* __restrict__ x, const float* __restrict__ shp,
    float* __restrict__ out)
{
    extern __shared__ __align__(16) unsigned char smem_raw[];
    float*  xs   = (float*)smem_raw;                       // CC*LL = 6144 floats
    float2* shs2 = (float2*)(xs + CC * LL);                // CC*NPAIR*65 float2
    float2* sqs2 = shs2 + CC * NPAIR * 65;                 // CC*NPAIR float2
    __shared__ float red[8][NPAIR][2];

    const int b     = blockIdx.y;
    const int ntile = blockIdx.x;      // 0..7
    const int wsp   = blockIdx.z;      // 0..3
    const int tid   = threadIdx.x;
    const int npair = tid & (NPAIR - 1);
    const int wg    = tid >> 4;        // 0..15
    const int warp  = tid >> 5;
    const int lane  = tid & 31;

    // Stage x rows (vectorized)
    {
        const float4* xp = (const float4*)(x + b * CC * LL);
        float4* xd = (float4*)xs;
        for (int i = tid; i < CC * LL / 4; i += THREADS) xd[i] = xp[i];
    }
    // Stage shapelet tile, n-pair interleaved: shs2[(c*NPAIR+p)*65+s] = (shp[c][n0][s], shp[c][n1][s])
    for (int i = tid; i < CC * NPAIR * SS; i += THREADS) {
        int c = i / (NPAIR * SS);
        int r = i - c * (NPAIR * SS);
        int p = r / SS, s = r - p * SS;
        int n0 = ntile * NT + 2 * p;
        float2 v;
        v.x = shp[(c * NN + n0) * SS + s];
        v.y = shp[(c * NN + n0 + 1) * SS + s];
        shs2[(c * NPAIR + p) * 65 + s] = v;
    }
    __syncthreads();

    // Shapelet squared norms per pair
    if (tid < CC * NPAIR) {
        int c = tid / NPAIR, p = tid - c * NPAIR;
        float a0 = 0.f, a1 = 0.f;
#pragma unroll 8
        for (int s = 0; s < SS; s++) {
            float2 v = shs2[(c * NPAIR + p) * 65 + s];
            a0 = fmaf(v.x, v.x, a0);
            a1 = fmaf(v.y, v.y, a1);
        }
        sqs2[tid] = make_float2(a0, a1);
    }
    __syncthreads();

    // Preload per-c shapelet norm pairs and row pointers
    unsigned long long sqn2[CC];
#pragma unroll
    for (int c = 0; c < CC; c++) {
        float2 q = sqs2[c * NPAIR + npair];
        unsigned long long r;
        asm("mov.b64 %0, {%1, %2};" : "=l"(r) : "f"(q.x), "f"(q.y));
        sqn2[c] = r;
    }
    const unsigned long long NEG2 = pack2(-2.0f);

    float tmin0 = __int_as_float(0x7f800000);
    float tmin1 = __int_as_float(0x7f800000);

    for (int ci = 0; ci < CHUNK_PER_BLK; ci++) {
        const int cg = wsp * CHUNK_PER_BLK + ci;     // global chunk 0..15
        const int w0 = cg * (WG * WPT) + wg * WPT;   // up to 2040

        float t0[WPT], t1[WPT];
#pragma unroll
        for (int j = 0; j < WPT; j++) { t0[j] = 0.f; t1[j] = 0.f; }

#pragma unroll
        for (int c = 0; c < CC; c++) {
            const float* xc = xs + c * LL;
            const float2* shrow = shs2 + (c * NPAIR + npair) * 65;

            unsigned long long acc2[WPT];
#pragma unroll
            for (int j = 0; j < WPT; j++) acc2[j] = 0ull;

            // rolling packed window of 8 x values
            unsigned long long xw2[8];
#pragma unroll
            for (int k = 0; k < 8; k++) xw2[k] = pack2(xc[min(w0 + k, LL - 1)]);

            for (int sb = 0; sb < SS; sb += 8) {
#pragma unroll
                for (int u = 0; u < 8; u++) {
                    int s = sb + u;
                    unsigned long long sh2 = *(const unsigned long long*)(shrow + s);
#pragma unroll
                    for (int j = 0; j < WPT; j++)
                        fma2(acc2[j], xw2[(u + j) & 7], sh2);
                    // load x for step s+8 into the expired slot
                    xw2[u] = pack2(xc[min(w0 + s + 8, LL - 1)]);
                }
            }

            // epilogue: d2 = ws + sqn - 2*cross, accumulate sqrt
            const float* wsrow = g_winsq + (b * CC + c) * WPAD + w0;
            float4 wsa = __ldg((const float4*)wsrow);
            float4 wsb = __ldg((const float4*)(wsrow + 4));
            float wsv[8] = {wsa.x, wsa.y, wsa.z, wsa.w, wsb.x, wsb.y, wsb.z, wsb.w};
#pragma unroll
            for (int j = 0; j < WPT; j++) {
                unsigned long long base = add2(pack2(wsv[j]), sqn2[c]);
                fma2(base, acc2[j], NEG2);          // base = ws+sq - 2*cross
                float lo, hi;
                unpack2(lo, hi, base);
                t0[j] += sqrtf(fmaxf(lo, 0.f));
                t1[j] += sqrtf(fmaxf(hi, 0.f));
            }
        }

#pragma unroll
        for (int j = 0; j < WPT; j++) {
            if (w0 + j < WW) {
                tmin0 = fminf(tmin0, t0[j]);
                tmin1 = fminf(tmin1, t1[j]);
            }
        }
    }

    // reduce across the 16 w-groups: first lane bit 4 (wg parity), then smem
    tmin0 = fminf(tmin0, __shfl_xor_sync(0xffffffffu, tmin0, 16));
    tmin1 = fminf(tmin1, __shfl_xor_sync(0xffffffffu, tmin1, 16));
    if (lane < NPAIR) {
        red[warp][lane][0] = tmin0;
        red[warp][lane][1] = tmin1;
    }
    __syncthreads();
    if (tid < NPAIR) {
        float m0 = red[0][tid][0], m1 = red[0][tid][1];
#pragma unroll
        for (int wr = 1; wr < 8; wr++) {
            m0 = fminf(m0, red[wr][tid][0]);
            m1 = fminf(m1, red[wr][tid][1]);
        }
        unsigned int* ob = (unsigned int*)(out + b * NN + ntile * NT + 2 * tid);
        atomicMin(ob,     __float_as_uint(m0));
        atomicMin(ob + 1, __float_as_uint(m1));
    }
}

extern "C" void kernel_launch(void* const* d_in, const int* in_sizes, int n_in,
                              void* d_out, int out_size) {
    (void)in_sizes; (void)n_in; (void)out_size;
    const float* x   = (const float*)d_in[0];
    const float* shp = (const float*)d_in[1];
    float* out = (float*)d_out;

    const int smem_bytes = CC * LL * 4 + CC * NPAIR * 65 * 8 + CC * NPAIR * 8;
    static int configured = -1;
    cudaFuncSetAttribute(main_kernel, cudaFuncAttributeMaxDynamicSharedMemorySize, smem_bytes);
    (void)configured;

    init_kernel<<<(BB * NN + 255) / 256, 256>>>(out);
    winsq_kernel<<<dim3(BB, CC), 256>>>(x);
    main_kernel<<<dim3(NN / NT, BB, WSPLIT), THREADS, smem_bytes>>>(x, shp, out);
}

// round 4
// speedup vs baseline: 4.0057x; 1.2370x over previous
#include <cuda_runtime.h>
#include <math.h>
#include <stdint.h>

#define SS 64
#define NN 256
#define CC 3
#define BB 64
#define LL 2048
#define WW (LL - SS + 1)   /* 1985 */
#define WPAD 2048
#define NT 32              /* shapelets per block */
#define NPAIR 16
#define WG 16              /* w-groups (threads dim) */
#define WPT 8              /* w per thread per chunk */
#define WSLICE 8           /* w slices (blockIdx.z) */
#define WPB 256            /* w per block */
#define CHUNKS 2           /* 2 x 128 w per block */
#define XS 320             /* staged x values per channel: 248+71+pad */
#define THREADS 256

__device__ float g_winsq[BB * CC * WPAD];

// ---------- packed f32x2 helpers (sm_103a fma pipe, 2x fp32 throughput) ----------
__device__ __forceinline__ unsigned long long pack2(float v) {
    unsigned long long r;
    asm("mov.b64 %0, {%1, %1};" : "=l"(r) : "f"(v));
    return r;
}
__device__ __forceinline__ void fma2(unsigned long long& d, unsigned long long a,
                                     unsigned long long b) {
    asm("fma.rn.f32x2 %0, %1, %2, %0;" : "+l"(d) : "l"(a), "l"(b));
}
__device__ __forceinline__ unsigned long long add2(unsigned long long a,
                                                   unsigned long long b) {
    unsigned long long r;
    asm("add.rn.f32x2 %0, %1, %2;" : "=l"(r) : "l"(a), "l"(b));
    return r;
}
__device__ __forceinline__ void unpack2(float& lo, float& hi, unsigned long long v) {
    asm("mov.b64 {%0, %1}, %2;" : "=f"(lo), "=f"(hi) : "l"(v));
}
__device__ __forceinline__ float sqrt_ap(float v) {
    float r;
    asm("sqrt.approx.f32 %0, %1;" : "=f"(r) : "f"(v));
    return r;
}

// ---------- kernel 1: window squared norms + output init (fused) ----------
__global__ void winsq_kernel(const float* __restrict__ x, float* __restrict__ out) {
    int b = blockIdx.x, c = blockIdx.y;
    __shared__ float xs[LL];
    const float* xp = x + (b * CC + c) * LL;
    for (int i = threadIdx.x; i < LL; i += blockDim.x) xs[i] = xp[i];
    if (c == 0)  // 64 blocks x 256 threads == BB*NN exactly
        out[b * 256 + threadIdx.x] = __int_as_float(0x7f800000);
    __syncthreads();
    for (int w = threadIdx.x; w < WPAD; w += blockDim.x) {
        float s = 0.f;
        if (w < WW) {
#pragma unroll 16
            for (int k = 0; k < SS; k++) { float v = xs[w + k]; s = fmaf(v, v, s); }
        }
        g_winsq[(b * CC + c) * WPAD + w] = s;
    }
}

// ---------- kernel 2: main ----------
__global__ __launch_bounds__(THREADS, 3) void main_kernel(
    const float* __restrict__ x, const float* __restrict__ shp,
    float* __restrict__ out)
{
    extern __shared__ __align__(16) unsigned char smem_raw[];
    float2* xd   = (float2*)smem_raw;                 // CC*XS duplicated pairs (7680 B)
    float2* shs2 = xd + CC * XS;                      // CC*NPAIR*65 (24960 B)
    float*  wss  = (float*)(shs2 + CC * NPAIR * 65);  // CC*WPB (3072 B)
    float2* sqs2 = (float2*)(wss + CC * WPB);         // CC*NPAIR (384 B)
    __shared__ float red[8][NPAIR][2];

    const int ntile = blockIdx.x;      // 0..7
    const int b     = blockIdx.y;      // 0..63
    const int wsl   = blockIdx.z;      // 0..7
    const int tid   = threadIdx.x;
    const int npair = tid & (NPAIR - 1);
    const int wg    = tid >> 4;        // 0..15
    const int warp  = tid >> 5;
    const int lane  = tid & 31;
    const int wbase = wsl * WPB;

    // Stage x window as duplicated pairs (clamped)
    for (int i = tid; i < CC * XS; i += THREADS) {
        int c = i / XS, j = i - c * XS;
        float v = x[(b * CC + c) * LL + min(wbase + j, LL - 1)];
        xd[i] = make_float2(v, v);
    }
    // Stage shapelet tile, n-pair interleaved, pad 65
    for (int i = tid; i < CC * NPAIR * SS; i += THREADS) {
        int c = i / (NPAIR * SS);
        int r = i - c * (NPAIR * SS);
        int p = r / SS, s = r - p * SS;
        int n0 = ntile * NT + 2 * p;
        float2 v;
        v.x = shp[(c * NN + n0) * SS + s];
        v.y = shp[(c * NN + n0 + 1) * SS + s];
        shs2[(c * NPAIR + p) * 65 + s] = v;
    }
    // Stage winsq slice (WPAD row => no OOB)
    for (int i = tid; i < CC * WPB; i += THREADS) {
        int c = i >> 8, j = i & 255;
        wss[i] = g_winsq[(b * CC + c) * WPAD + wbase + j];
    }
    __syncthreads();

    // Shapelet squared norms per pair
    if (tid < CC * NPAIR) {
        int c = tid / NPAIR, p = tid - c * NPAIR;
        float a0 = 0.f, a1 = 0.f;
#pragma unroll 8
        for (int s = 0; s < SS; s++) {
            float2 v = shs2[(c * NPAIR + p) * 65 + s];
            a0 = fmaf(v.x, v.x, a0);
            a1 = fmaf(v.y, v.y, a1);
        }
        sqs2[tid] = make_float2(a0, a1);
    }
    __syncthreads();

    unsigned long long sqn2[CC];
#pragma unroll
    for (int c = 0; c < CC; c++) {
        float2 q = sqs2[c * NPAIR + npair];
        unsigned long long r;
        asm("mov.b64 %0, {%1, %2};" : "=l"(r) : "f"(q.x), "f"(q.y));
        sqn2[c] = r;
    }
    const unsigned long long NEG2 = pack2(-2.0f);
    const float INF = __int_as_float(0x7f800000);
    float tmin0 = INF, tmin1 = INF;

#pragma unroll
    for (int chunk = 0; chunk < CHUNKS; chunk++) {
        const int w0l = chunk * (WG * WPT) + wg * WPT;   // local w, 0..248

        float t0[WPT], t1[WPT];
#pragma unroll
        for (int j = 0; j < WPT; j++) { t0[j] = 0.f; t1[j] = 0.f; }

#pragma unroll
        for (int c = 0; c < CC; c++) {
            const unsigned long long* xr =
                (const unsigned long long*)(xd + c * XS + w0l);
            const unsigned long long* shrow =
                (const unsigned long long*)(shs2 + (c * NPAIR + npair) * 65);

            unsigned long long acc2[WPT];
#pragma unroll
            for (int j = 0; j < WPT; j++) acc2[j] = 0ull;

            // rolling packed window of 8 duplicated x pairs
            unsigned long long xw2[8];
#pragma unroll
            for (int k = 0; k < 8; k++) xw2[k] = xr[k];

            for (int sb = 0; sb < SS; sb += 8) {
#pragma unroll
                for (int u = 0; u < 8; u++) {
                    int s = sb + u;
                    unsigned long long sh2 = shrow[s];
#pragma unroll
                    for (int j = 0; j < WPT; j++)
                        fma2(acc2[j], xw2[(u + j) & 7], sh2);
                    xw2[u] = xr[s + 8];   // max index w0l+71 <= 319
                }
            }

            // epilogue: d2 = ws + sqn - 2*cross
            const float* wsrow = wss + c * WPB + w0l;
#pragma unroll
            for (int j = 0; j < WPT; j++) {
                unsigned long long base = add2(pack2(wsrow[j]), sqn2[c]);
                fma2(base, acc2[j], NEG2);
                float lo, hi;
                unpack2(lo, hi, base);
                t0[j] += sqrt_ap(fmaxf(lo, 0.f));
                t1[j] += sqrt_ap(fmaxf(hi, 0.f));
            }
        }

#pragma unroll
        for (int j = 0; j < WPT; j++) {
            if (wbase + w0l + j < WW) {
                tmin0 = fminf(tmin0, t0[j]);
                tmin1 = fminf(tmin1, t1[j]);
            }
        }
    }

    // reduce across 16 w-groups: lane bit 4, then cross-warp via smem
    tmin0 = fminf(tmin0, __shfl_xor_sync(0xffffffffu, tmin0, 16));
    tmin1 = fminf(tmin1, __shfl_xor_sync(0xffffffffu, tmin1, 16));
    if (lane < NPAIR) {
        red[warp][lane][0] = tmin0;
        red[warp][lane][1] = tmin1;
    }
    __syncthreads();
    if (tid < NPAIR) {
        float m0 = red[0][tid][0], m1 = red[0][tid][1];
#pragma unroll
        for (int wr = 1; wr < 8; wr++) {
            m0 = fminf(m0, red[wr][tid][0]);
            m1 = fminf(m1, red[wr][tid][1]);
        }
        unsigned int* ob = (unsigned int*)(out + b * NN + ntile * NT + 2 * tid);
        atomicMin(ob,     __float_as_uint(m0));
        atomicMin(ob + 1, __float_as_uint(m1));
    }
}

extern "C" void kernel_launch(void* const* d_in, const int* in_sizes, int n_in,
                              void* d_out, int out_size) {
    (void)in_sizes; (void)n_in; (void)out_size;
    const float* x   = (const float*)d_in[0];
    const float* shp = (const float*)d_in[1];
    float* out = (float*)d_out;

    const int smem_bytes = CC * XS * 8 + CC * NPAIR * 65 * 8 + CC * WPB * 4 + CC * NPAIR * 8;
    cudaFuncSetAttribute(main_kernel, cudaFuncAttributeMaxDynamicSharedMemorySize, smem_bytes);

    winsq_kernel<<<dim3(BB, CC), 256>>>(x, out);
    main_kernel<<<dim3(NN / NT, BB, WSLICE), THREADS, smem_bytes>>>(x, shp, out);
}